// round 1
// baseline (speedup 1.0000x reference)
#include <cuda_runtime.h>

#define PI_F 3.14159265358979323846f

// One thread per batch element. Exploits:
//   * xf == axes exactly (homography applied to its own source points)
//   * closed-form 2x2 Kabsch (no SVD, sqrt cancels)
//   * sort-invariance of the Procrustes cross-covariance K
__global__ void __launch_bounds__(256) cuboid_align_kernel(
    const float* __restrict__ top,   // [B,4,2]
    const float* __restrict__ bot,   // [B,4,2]
    float* __restrict__ out,         // [2,B,4,3] : top_points then bottom_points
    int B)
{
    int b = blockIdx.x * blockDim.x + threadIdx.x;
    if (b >= B) return;

    const float4* bp = (const float4*)bot + (size_t)b * 2;
    const float4* tp = (const float4*)top + (size_t)b * 2;
    float4 bq0 = bp[0], bq1 = bp[1];
    float4 tq0 = tp[0], tq1 = tp[1];

    float u[4]  = {bq0.x, bq0.z, bq1.x, bq1.z};
    float vv[4] = {bq0.y, bq0.w, bq1.y, bq1.w};
    float tv[4] = {tq0.y, tq0.w, tq1.y, tq1.w};

    // floor_xy + ceiling z accumulation
    float px[4], py[4];
    float czs = 0.f;
#pragma unroll
    for (int i = 0; i < 4; ++i) {
        float U = u[i] * PI_F;
        float V = vv[i] * (-0.5f * PI_F);
        float c = (-1.6f) / tanf(V);       // floor_z / tan(v)
        float s, co;
        sincosf(U, &s, &co);
        px[i] = c * s;
        py[i] = -c * co;
        float cn = sqrtf(px[i]*px[i] + py[i]*py[i]);
        czs += cn * tanf(tv[i] * (-0.5f * PI_F));
    }
    float ceil_z = 0.25f * czs;
    float cx = 0.25f * (px[0] + px[1] + px[2] + px[3]);
    float cy = 0.25f * (py[0] + py[1] + py[2] + py[3]);

    // edge-length based scale: scale = [a_y, a_x] / 2
    float dx, dy;
    dx = px[0]-px[1]; dy = py[0]-py[1]; float ax1 = sqrtf(dx*dx + dy*dy);
    dx = px[1]-px[2]; dy = py[1]-py[2]; float ay1 = sqrtf(dx*dx + dy*dy);
    dx = px[2]-px[3]; dy = py[2]-py[3]; float ax2 = sqrtf(dx*dx + dy*dy);
    dx = px[3]-px[0]; dy = py[3]-py[0]; float ay2 = sqrtf(dx*dx + dy*dy);
    float sx = 0.25f * (ay1 + ay2);   // multiplies x (scale[...,0] = a_y/2)
    float sy = 0.25f * (ax1 + ax2);   // multiplies y (scale[...,1] = a_x/2)

    // centered floor points
    float fx[4], fy[4];
#pragma unroll
    for (int i = 0; i < 4; ++i) { fx[i] = px[i] - cx; fy[i] = py[i] - cy; }

    // Procrustes cross-covariance K = sum_k (scale .* cub_k) (fx_k)^T
    // (permutation-invariant: both sides indexed through the same argsort)
    const float cubx[4] = {-1.f, -1.f,  1.f, 1.f};
    const float cuby[4] = { 1.f, -1.f, -1.f, 1.f};
    float Sxx = 0.f, Sxy = 0.f, Syx = 0.f, Syy = 0.f;
#pragma unroll
    for (int i = 0; i < 4; ++i) {
        Sxx += cubx[i] * fx[i];
        Sxy += cubx[i] * fy[i];
        Syx += cuby[i] * fx[i];
        Syy += cuby[i] * fy[i];
    }
    float Ka = sx * Sxx, Kb = sx * Sxy, Kc = sy * Syx, Kd = sy * Syy;
    float var = 4.f * (sx*sx + sy*sy);
    float alpha = (Ka + Kd) / var;   // scale_p * cos(theta)
    float beta  = (Kb - Kc) / var;   // scale_p * sin(theta)

    // final rectified points per cuboid-corner index m
    float Px[4], Py[4];
#pragma unroll
    for (int m = 0; m < 4; ++m) {
        float wx = sx * cubx[m];
        float wy = sy * cuby[m];
        Px[m] = cx + alpha * wx - beta * wy;
        Py[m] = cy + beta  * wx + alpha * wy;
    }

    // output ordering: argsort of atan2(fx, fy + 1e-12)
    float key[4];
#pragma unroll
    for (int i = 0; i < 4; ++i) key[i] = atan2f(fx[i], fy[i] + 1e-12f);
    int i0 = 0, i1 = 1, i2 = 2, i3 = 3;
    float k0 = key[0], k1 = key[1], k2 = key[2], k3 = key[3];
    float kt; int it;
    // sorting network (ascending): (0,1)(2,3)(0,2)(1,3)(1,2)
    if (k0 > k1) { kt=k0;k0=k1;k1=kt; it=i0;i0=i1;i1=it; }
    if (k2 > k3) { kt=k2;k2=k3;k3=kt; it=i2;i2=i3;i3=it; }
    if (k0 > k2) { kt=k0;k0=k2;k2=kt; it=i0;i0=i2;i2=it; }
    if (k1 > k3) { kt=k1;k1=k3;k3=kt; it=i1;i1=i3;i3=it; }
    if (k1 > k2) { kt=k1;k1=k2;k2=kt; it=i1;i1=i2;i2=it; }

    int ord[4] = {i0, i1, i2, i3};

    float ot[12], ob[12];
#pragma unroll
    for (int j = 0; j < 4; ++j) {
        int m = ord[j];
        ot[j*3+0] = Px[m]; ot[j*3+1] = Py[m]; ot[j*3+2] = ceil_z;
        ob[j*3+0] = Px[m]; ob[j*3+1] = Py[m]; ob[j*3+2] = -1.6f;
    }

    float4* o_top = (float4*)(out + (size_t)b * 12);
    float4* o_bot = (float4*)(out + (size_t)B * 12 + (size_t)b * 12);
    o_top[0] = make_float4(ot[0], ot[1], ot[2],  ot[3]);
    o_top[1] = make_float4(ot[4], ot[5], ot[6],  ot[7]);
    o_top[2] = make_float4(ot[8], ot[9], ot[10], ot[11]);
    o_bot[0] = make_float4(ob[0], ob[1], ob[2],  ob[3]);
    o_bot[1] = make_float4(ob[4], ob[5], ob[6],  ob[7]);
    o_bot[2] = make_float4(ob[8], ob[9], ob[10], ob[11]);
}

extern "C" void kernel_launch(void* const* d_in, const int* in_sizes, int n_in,
                              void* d_out, int out_size)
{
    const float* top = (const float*)d_in[0];  // top_corners  [B,4,2]
    const float* bot = (const float*)d_in[1];  // bottom_corners [B,4,2]
    // d_in[2] = cuboid_axes (constant [[-1,1],[-1,-1],[1,-1],[1,1]], hardcoded)
    int B = in_sizes[0] / 8;
    int threads = 256;
    int blocks = (B + threads - 1) / threads;
    cuboid_align_kernel<<<blocks, threads>>>(top, bot, (float*)d_out, B);
}

// round 2
// speedup vs baseline: 1.1605x; 1.1605x over previous
#include <cuda_runtime.h>

#define PI_F     3.14159265358979323846f
#define FLOOR_Z  (-1.6f)

__device__ __forceinline__ float fast_sqrt(float x) {
    float r;
    asm("sqrt.approx.f32 %0, %1;" : "=f"(r) : "f"(x));
    return r;
}

// One thread per batch element. Closed-form pipeline:
//   * xf == axes exactly (homography applied to its own source points)
//   * closed-form 2x2 Kabsch (no SVD; sqrt cancels)
//   * sort-invariant Procrustes cross-covariance
//   * pseudo-angle sort key (monotonic with atan2) + tuple sorting network
__global__ void __launch_bounds__(256) cuboid_align_kernel(
    const float* __restrict__ top,   // [B,4,2]
    const float* __restrict__ bot,   // [B,4,2]
    float* __restrict__ out,         // [2,B,4,3] : top_points then bottom_points
    int B)
{
    int b = blockIdx.x * blockDim.x + threadIdx.x;
    if (b >= B) return;

    const float4* bp = (const float4*)bot + (size_t)b * 2;
    const float4* tp = (const float4*)top + (size_t)b * 2;
    float4 bq0 = bp[0], bq1 = bp[1];
    float4 tq0 = tp[0], tq1 = tp[1];

    float u[4]  = {bq0.x, bq0.z, bq1.x, bq1.z};
    float vv[4] = {bq0.y, bq0.w, bq1.y, bq1.w};
    float tv[4] = {tq0.y, tq0.w, tq1.y, tq1.w};

    // floor_xy + ceiling z accumulation (all MUFU-approx transcendentals)
    float px[4], py[4];
    float czs = 0.f;
#pragma unroll
    for (int i = 0; i < 4; ++i) {
        float U = u[i] * PI_F;
        float V = vv[i] * (-0.5f * PI_F);
        // c = FLOOR_Z / tan(V) = FLOOR_Z * cos(V) / sin(V)
        float sv = __sinf(V), cv = __cosf(V);
        float c = __fdividef(FLOOR_Z * cv, sv);
        float s, co;
        __sincosf(U, &s, &co);
        px[i] = c * s;
        py[i] = -c * co;
        float cn = fast_sqrt(px[i]*px[i] + py[i]*py[i]);
        czs += cn * __tanf(tv[i] * (-0.5f * PI_F));
    }
    float ceil_z = 0.25f * czs;
    float cx = 0.25f * (px[0] + px[1] + px[2] + px[3]);
    float cy = 0.25f * (py[0] + py[1] + py[2] + py[3]);

    // edge-length based scale: scale = [a_y, a_x] / 2
    float dx, dy;
    dx = px[0]-px[1]; dy = py[0]-py[1]; float ax1 = fast_sqrt(dx*dx + dy*dy);
    dx = px[1]-px[2]; dy = py[1]-py[2]; float ay1 = fast_sqrt(dx*dx + dy*dy);
    dx = px[2]-px[3]; dy = py[2]-py[3]; float ax2 = fast_sqrt(dx*dx + dy*dy);
    dx = px[3]-px[0]; dy = py[3]-py[0]; float ay2 = fast_sqrt(dx*dx + dy*dy);
    float sx = 0.25f * (ay1 + ay2);   // scale[...,0] = a_y/2 (multiplies x)
    float sy = 0.25f * (ax1 + ax2);   // scale[...,1] = a_x/2 (multiplies y)

    // centered floor points
    float fx[4], fy[4];
#pragma unroll
    for (int i = 0; i < 4; ++i) { fx[i] = px[i] - cx; fy[i] = py[i] - cy; }

    // Procrustes cross-covariance K = sum_i (scale .* cub_i) (fx_i)^T
    const float cubx[4] = {-1.f, -1.f,  1.f, 1.f};
    const float cuby[4] = { 1.f, -1.f, -1.f, 1.f};
    float Sxx = 0.f, Sxy = 0.f, Syx = 0.f, Syy = 0.f;
#pragma unroll
    for (int i = 0; i < 4; ++i) {
        Sxx += cubx[i] * fx[i];
        Sxy += cubx[i] * fy[i];
        Syx += cuby[i] * fx[i];
        Syy += cuby[i] * fy[i];
    }
    float var   = 4.f * (sx*sx + sy*sy);
    float rvar  = __fdividef(1.f, var);
    float alpha = (sx * Sxx + sy * Syy) * rvar;   // scale_p * cos(theta)
    float beta  = (sx * Sxy - sy * Syx) * rvar;   // scale_p * sin(theta)

    // final rectified point for corner-index i, plus its pseudo-angle key.
    // key monotonic with atan2(fx, fy + 1e-12):
    //   p = copysign(1 - Y/(|X|+|Y|), X),  X = fx, Y = fy + 1e-12
    float K0, K1, K2, K3;
    float PX0, PX1, PX2, PX3, PY0, PY1, PY2, PY3;
#pragma unroll
    for (int i = 0; i < 4; ++i) {
        float wx = sx * cubx[i];
        float wy = sy * cuby[i];
        float Pxi = cx + alpha * wx - beta * wy;
        float Pyi = cy + beta  * wx + alpha * wy;
        float X = fx[i], Y = fy[i] + 1e-12f;
        float t = __fdividef(Y, fabsf(X) + fabsf(Y));
        float k = copysignf(1.f - t, X);
        if (i == 0) { K0 = k; PX0 = Pxi; PY0 = Pyi; }
        if (i == 1) { K1 = k; PX1 = Pxi; PY1 = Pyi; }
        if (i == 2) { K2 = k; PX2 = Pxi; PY2 = Pyi; }
        if (i == 3) { K3 = k; PX3 = Pxi; PY3 = Pyi; }
    }

    // 5-comparator sorting network on (key, Px, Py) tuples — registers only
    float t_;
#define CSWAP(ka, kb, xa, xb, ya, yb)                                   \
    if (ka > kb) { t_=ka;ka=kb;kb=t_; t_=xa;xa=xb;xb=t_; t_=ya;ya=yb;yb=t_; }
    CSWAP(K0, K1, PX0, PX1, PY0, PY1)
    CSWAP(K2, K3, PX2, PX3, PY2, PY3)
    CSWAP(K0, K2, PX0, PX2, PY0, PY2)
    CSWAP(K1, K3, PX1, PX3, PY1, PY3)
    CSWAP(K1, K2, PX1, PX2, PY1, PY2)
#undef CSWAP

    float4* o_top = (float4*)(out + (size_t)b * 12);
    float4* o_bot = (float4*)(out + (size_t)B * 12 + (size_t)b * 12);
    o_top[0] = make_float4(PX0, PY0, ceil_z, PX1);
    o_top[1] = make_float4(PY1, ceil_z, PX2, PY2);
    o_top[2] = make_float4(ceil_z, PX3, PY3, ceil_z);
    o_bot[0] = make_float4(PX0, PY0, FLOOR_Z, PX1);
    o_bot[1] = make_float4(PY1, FLOOR_Z, PX2, PY2);
    o_bot[2] = make_float4(FLOOR_Z, PX3, PY3, FLOOR_Z);
}

extern "C" void kernel_launch(void* const* d_in, const int* in_sizes, int n_in,
                              void* d_out, int out_size)
{
    const float* top = (const float*)d_in[0];  // top_corners   [B,4,2]
    const float* bot = (const float*)d_in[1];  // bottom_corners [B,4,2]
    // d_in[2] = cuboid_axes (constant [[-1,1],[-1,-1],[1,-1],[1,1]], hardcoded)
    int B = in_sizes[0] / 8;
    int threads = 256;
    int blocks = (B + threads - 1) / threads;
    cuboid_align_kernel<<<blocks, threads>>>(top, bot, (float*)d_out, B);
}